// round 1
// baseline (speedup 1.0000x reference)
#include <cuda_runtime.h>
#include <cuda_bf16.h>
#include <cstdint>

#define DEVI static __device__ __forceinline__

static constexpr int MT = 64 * 197;   // 12608 rows
static constexpr int DD = 768;
static constexpr int HH = 3072;
static constexpr float FBIG = 3.0e38f;

// Scratch (allocation-free rule: __device__ globals)
__device__ __nv_bfloat16 g_xq[MT * DD];          // quantized x codes (q - zp), exact ints in bf16
__device__ __nv_bfloat16 g_w1q[HH * DD];         // quantized w1 codes
__device__ __nv_bfloat16 g_w2q[DD * HH];         // quantized w2 codes
__device__ float         g_mid[(size_t)MT * HH]; // gelu output, fp32
__device__ __nv_bfloat16 g_gq[(size_t)MT * HH];  // quantized g codes
__device__ float         g_stats[6];             // xmin,xmax,w1max,w2max,gmin,gmax

DEVI void atomicMinF(float* a, float v) {
    int* ai = (int*)a;
    int old = *ai;
    while (__int_as_float(old) > v) {
        int as = old;
        old = atomicCAS(ai, as, __float_as_int(v));
        if (old == as) break;
    }
}
DEVI void atomicMaxF(float* a, float v) {
    int* ai = (int*)a;
    int old = *ai;
    while (__int_as_float(old) < v) {
        int as = old;
        old = atomicCAS(ai, as, __float_as_int(v));
        if (old == as) break;
    }
}

__global__ void k_init() {
    g_stats[0] = FBIG;  g_stats[1] = -FBIG;
    g_stats[2] = 0.f;   g_stats[3] = 0.f;
    g_stats[4] = FBIG;  g_stats[5] = -FBIG;
}

__global__ void k_minmax(const float* __restrict__ x, int n4, int idx) {
    float lo = FBIG, hi = -FBIG;
    int st = gridDim.x * blockDim.x;
    for (int i = blockIdx.x * blockDim.x + threadIdx.x; i < n4; i += st) {
        float4 v = ((const float4*)x)[i];
        lo = fminf(lo, fminf(fminf(v.x, v.y), fminf(v.z, v.w)));
        hi = fmaxf(hi, fmaxf(fmaxf(v.x, v.y), fmaxf(v.z, v.w)));
    }
    for (int o = 16; o; o >>= 1) {
        lo = fminf(lo, __shfl_xor_sync(0xffffffffu, lo, o));
        hi = fmaxf(hi, __shfl_xor_sync(0xffffffffu, hi, o));
    }
    __shared__ float slo[8], shi[8];
    int w = threadIdx.x >> 5;
    if ((threadIdx.x & 31) == 0) { slo[w] = lo; shi[w] = hi; }
    __syncthreads();
    if (threadIdx.x == 0) {
        for (int i = 1; i < 8; i++) { lo = fminf(lo, slo[i]); hi = fmaxf(hi, shi[i]); }
        atomicMinF(&g_stats[idx], lo);
        atomicMaxF(&g_stats[idx + 1], hi);
    }
}

__global__ void k_absmax(const float* __restrict__ w, int n4, int idx) {
    float hi = 0.f;
    int st = gridDim.x * blockDim.x;
    for (int i = blockIdx.x * blockDim.x + threadIdx.x; i < n4; i += st) {
        float4 v = ((const float4*)w)[i];
        hi = fmaxf(hi, fmaxf(fmaxf(fabsf(v.x), fabsf(v.y)), fmaxf(fabsf(v.z), fabsf(v.w))));
    }
    for (int o = 16; o; o >>= 1) hi = fmaxf(hi, __shfl_xor_sync(0xffffffffu, hi, o));
    __shared__ float shi[8];
    int w8 = threadIdx.x >> 5;
    if ((threadIdx.x & 31) == 0) shi[w8] = hi;
    __syncthreads();
    if (threadIdx.x == 0) {
        for (int i = 1; i < 8; i++) hi = fmaxf(hi, shi[i]);
        atomicMaxF(&g_stats[idx], hi);
    }
}

// asymmetric uint8 fake-quant of activations -> store (q - zp) as exact bf16 integer
DEVI float quant_act_one(float v, float s, float zp) {
    return fminf(fmaxf(rintf(v / s) + zp, 0.f), 255.f) - zp;
}

__global__ void k_quant_x(const float* __restrict__ x, int n4) {
    float lo = g_stats[0], hi = g_stats[1];
    float s = fmaxf(hi - lo, 1e-8f) / 255.0f;
    float zp = rintf(-lo / s);
    __nv_bfloat162* qp = (__nv_bfloat162*)g_xq;
    int st = gridDim.x * blockDim.x;
    for (int i = blockIdx.x * blockDim.x + threadIdx.x; i < n4; i += st) {
        float4 v = ((const float4*)x)[i];
        qp[2 * i]     = __floats2bfloat162_rn(quant_act_one(v.x, s, zp), quant_act_one(v.y, s, zp));
        qp[2 * i + 1] = __floats2bfloat162_rn(quant_act_one(v.z, s, zp), quant_act_one(v.w, s, zp));
    }
}

__global__ void k_quant_g(int n4) {
    float lo = g_stats[4], hi = g_stats[5];
    float s = fmaxf(hi - lo, 1e-8f) / 255.0f;
    float zp = rintf(-lo / s);
    __nv_bfloat162* qp = (__nv_bfloat162*)g_gq;
    const float* x = g_mid;
    int st = gridDim.x * blockDim.x;
    for (int i = blockIdx.x * blockDim.x + threadIdx.x; i < n4; i += st) {
        float4 v = ((const float4*)x)[i];
        qp[2 * i]     = __floats2bfloat162_rn(quant_act_one(v.x, s, zp), quant_act_one(v.y, s, zp));
        qp[2 * i + 1] = __floats2bfloat162_rn(quant_act_one(v.z, s, zp), quant_act_one(v.w, s, zp));
    }
}

// symmetric int8 fake-quant of weights -> store q as exact bf16 integer
__global__ void k_quant_w(const float* __restrict__ w, int n4, int idx, int which) {
    float s = fmaxf(g_stats[idx], 1e-8f) / 127.0f;
    __nv_bfloat162* qp = (__nv_bfloat162*)(which ? g_w2q : g_w1q);
    int st = gridDim.x * blockDim.x;
    for (int i = blockIdx.x * blockDim.x + threadIdx.x; i < n4; i += st) {
        float4 v = ((const float4*)w)[i];
        float q0 = fminf(fmaxf(rintf(v.x / s), -128.f), 127.f);
        float q1 = fminf(fmaxf(rintf(v.y / s), -128.f), 127.f);
        float q2 = fminf(fmaxf(rintf(v.z / s), -128.f), 127.f);
        float q3 = fminf(fmaxf(rintf(v.w / s), -128.f), 127.f);
        qp[2 * i]     = __floats2bfloat162_rn(q0, q1);
        qp[2 * i + 1] = __floats2bfloat162_rn(q2, q3);
    }
}

// I-BERT polynomial GELU
DEVI float igelu(float x) {
    float tt = x * 0.70710678118654752440f;
    float at = fminf(fabsf(tt), 1.769f);
    float dd = at - 1.769f;
    float L = fmaf(-0.2888f, dd * dd, 1.0f);   // always > 0
    L = copysignf(L, tt);
    return x * 0.5f * (1.0f + L);
}

// ---------------------------------------------------------------------------
// GEMM: C[m,n] = sc * sum_k A[m,k] * B[n,k]  + bias[n]   (TN, both K-major)
// EPI==1: A=g_xq, B=g_w1q, C=g_mid, epilogue = gelu + global min/max tracking
// EPI==2: A=g_gq, B=g_w2q, C=out,   epilogue = plain bias
// ---------------------------------------------------------------------------
template <int EPI>
__global__ void __launch_bounds__(256) k_gemm(const float* __restrict__ bias,
                                              float* __restrict__ Cout) {
    constexpr int BM = 128, BN = 64, BK = 32, SROW = 40;  // SROW pad: 16B aligned, conflict-free
    constexpr int Mn = MT;
    constexpr int Nn = (EPI == 1) ? HH : DD;
    constexpr int Kn = (EPI == 1) ? DD : HH;
    constexpr int KT = Kn / BK;

    const __nv_bfloat16* __restrict__ A = (EPI == 1) ? g_xq : g_gq;
    const __nv_bfloat16* __restrict__ B = (EPI == 1) ? g_w1q : g_w2q;
    float* __restrict__ C = (EPI == 1) ? g_mid : Cout;

    __shared__ __nv_bfloat16 smem[2 * (BM + BN) * SROW];
    __nv_bfloat16* sA0 = smem;
    __nv_bfloat16* sB0 = smem + BM * SROW;
    __nv_bfloat16* sA1 = smem + (BM + BN) * SROW;
    __nv_bfloat16* sB1 = sA1 + BM * SROW;

    const int tid = threadIdx.x;
    const int warp = tid >> 5, lane = tid & 31;
    const int wm = warp & 3, wn = warp >> 2;          // 4x2 warp grid, 32x32 per warp
    const int g = lane >> 2, t = lane & 3;
    const int mBase = blockIdx.x * BM, nBase = blockIdx.y * BN;
    const int lr = tid >> 2, lc = (tid & 3) * 8;      // cp.async: 16B chunks, 4 per 32-elem row

    float acc[2][4][4];
#pragma unroll
    for (int i = 0; i < 2; i++)
#pragma unroll
        for (int j = 0; j < 4; j++)
#pragma unroll
            for (int k = 0; k < 4; k++) acc[i][j][k] = 0.f;

    auto issue = [&](int kt, __nv_bfloat16* sA, __nv_bfloat16* sB) {
#pragma unroll
        for (int p = 0; p < 2; p++) {
            int row = lr + p * 64;
            int grow = mBase + row;
            bool ok = grow < Mn;
            int safe = ok ? grow : (Mn - 1);
            const __nv_bfloat16* gp = A + (size_t)safe * Kn + (size_t)kt * BK + lc;
            uint32_t sa = (uint32_t)__cvta_generic_to_shared(sA + row * SROW + lc);
            int sz = ok ? 16 : 0;  // src-size 0 => zero-fill
            asm volatile("cp.async.cg.shared.global [%0], [%1], 16, %2;\n"
                         :: "r"(sa), "l"(gp), "r"(sz));
        }
        {
            const __nv_bfloat16* gp = B + (size_t)(nBase + lr) * Kn + (size_t)kt * BK + lc;
            uint32_t sa = (uint32_t)__cvta_generic_to_shared(sB + lr * SROW + lc);
            asm volatile("cp.async.cg.shared.global [%0], [%1], 16, %2;\n"
                         :: "r"(sa), "l"(gp), "r"(16));
        }
        asm volatile("cp.async.commit_group;\n");
    };

    auto compute = [&](const __nv_bfloat16* sA, const __nv_bfloat16* sB) {
        const uint32_t* A32 = (const uint32_t*)sA;
        const uint32_t* B32 = (const uint32_t*)sB;
#pragma unroll
        for (int ks = 0; ks < 2; ks++) {
            const int k2 = ks * 8;  // k offset in 4B words
            uint32_t af[2][4], bfg[4][2];
#pragma unroll
            for (int i = 0; i < 2; i++) {
                int r0 = (wm * 32 + i * 16 + g) * (SROW / 2);
                af[i][0] = A32[r0 + k2 + t];
                af[i][1] = A32[r0 + 8 * (SROW / 2) + k2 + t];
                af[i][2] = A32[r0 + k2 + 4 + t];
                af[i][3] = A32[r0 + 8 * (SROW / 2) + k2 + 4 + t];
            }
#pragma unroll
            for (int j = 0; j < 4; j++) {
                int n0 = (wn * 32 + j * 8 + g) * (SROW / 2);
                bfg[j][0] = B32[n0 + k2 + t];
                bfg[j][1] = B32[n0 + k2 + 4 + t];
            }
#pragma unroll
            for (int i = 0; i < 2; i++)
#pragma unroll
                for (int j = 0; j < 4; j++) {
                    asm volatile(
                        "mma.sync.aligned.m16n8k16.row.col.f32.bf16.bf16.f32 "
                        "{%0,%1,%2,%3}, {%4,%5,%6,%7}, {%8,%9}, {%0,%1,%2,%3};\n"
                        : "+f"(acc[i][j][0]), "+f"(acc[i][j][1]),
                          "+f"(acc[i][j][2]), "+f"(acc[i][j][3])
                        : "r"(af[i][0]), "r"(af[i][1]), "r"(af[i][2]), "r"(af[i][3]),
                          "r"(bfg[j][0]), "r"(bfg[j][1]));
                }
        }
    };

    issue(0, sA0, sB0);
    for (int kt = 0; kt < KT; kt++) {
        __nv_bfloat16* cA = (kt & 1) ? sA1 : sA0;
        __nv_bfloat16* cB = (kt & 1) ? sB1 : sB0;
        if (kt + 1 < KT) {
            __nv_bfloat16* nA = (kt & 1) ? sA0 : sA1;
            __nv_bfloat16* nB = (kt & 1) ? sB0 : sB1;
            issue(kt + 1, nA, nB);
            asm volatile("cp.async.wait_group 1;\n");
        } else {
            asm volatile("cp.async.wait_group 0;\n");
        }
        __syncthreads();
        compute(cA, cB);
        __syncthreads();
    }

    // epilogue
    float sc;
    if (EPI == 1) {
        float s1 = fmaxf(g_stats[1] - g_stats[0], 1e-8f) / 255.0f;  // s_x
        float s2 = fmaxf(g_stats[2], 1e-8f) / 127.0f;               // s_w1
        sc = s1 * s2;
    } else {
        float s1 = fmaxf(g_stats[5] - g_stats[4], 1e-8f) / 255.0f;  // s_g
        float s2 = fmaxf(g_stats[3], 1e-8f) / 127.0f;               // s_w2
        sc = s1 * s2;
    }
    float lo = FBIG, hi = -FBIG;
#pragma unroll
    for (int i = 0; i < 2; i++) {
#pragma unroll
        for (int j = 0; j < 4; j++) {
            int c = nBase + wn * 32 + j * 8 + 2 * t;
            float bv0 = bias[c], bv1 = bias[c + 1];
#pragma unroll
            for (int h = 0; h < 2; h++) {
                int row = mBase + wm * 32 + i * 16 + g + h * 8;
                if (row < Mn) {
                    float v0 = sc * acc[i][j][2 * h + 0] + bv0;
                    float v1 = sc * acc[i][j][2 * h + 1] + bv1;
                    if (EPI == 1) {
                        v0 = igelu(v0);
                        v1 = igelu(v1);
                        lo = fminf(lo, fminf(v0, v1));
                        hi = fmaxf(hi, fmaxf(v0, v1));
                    }
                    C[(size_t)row * Nn + c]     = v0;
                    C[(size_t)row * Nn + c + 1] = v1;
                }
            }
        }
    }
    if (EPI == 1) {
        for (int o = 16; o; o >>= 1) {
            lo = fminf(lo, __shfl_xor_sync(0xffffffffu, lo, o));
            hi = fmaxf(hi, __shfl_xor_sync(0xffffffffu, hi, o));
        }
        __shared__ float rlo[8], rhi[8];
        if (lane == 0) { rlo[warp] = lo; rhi[warp] = hi; }
        __syncthreads();
        if (tid == 0) {
            for (int i = 1; i < 8; i++) { lo = fminf(lo, rlo[i]); hi = fmaxf(hi, rhi[i]); }
            atomicMinF(&g_stats[4], lo);
            atomicMaxF(&g_stats[5], hi);
        }
    }
}

extern "C" void kernel_launch(void* const* d_in, const int* in_sizes, int n_in,
                              void* d_out, int out_size) {
    const float* x  = (const float*)d_in[0];
    const float* w1 = (const float*)d_in[1];
    const float* b1 = (const float*)d_in[2];
    const float* w2 = (const float*)d_in[3];
    const float* b2 = (const float*)d_in[4];
    float* out = (float*)d_out;

    k_init<<<1, 1>>>();
    k_minmax<<<1024, 256>>>(x, MT * DD / 4, 0);
    k_absmax<<<512, 256>>>(w1, HH * DD / 4, 2);
    k_absmax<<<512, 256>>>(w2, DD * HH / 4, 3);
    k_quant_x<<<2048, 256>>>(x, MT * DD / 4);
    k_quant_w<<<512, 256>>>(w1, HH * DD / 4, 2, 0);
    k_quant_w<<<512, 256>>>(w2, DD * HH / 4, 3, 1);

    dim3 grid1((MT + 127) / 128, HH / 64);
    k_gemm<1><<<grid1, 256>>>(b1, nullptr);

    k_quant_g<<<4096, 256>>>((int)((size_t)MT * HH / 4));

    dim3 grid2((MT + 127) / 128, DD / 64);
    k_gemm<2><<<grid2, 256>>>(b2, out);
}